// round 7
// baseline (speedup 1.0000x reference)
#include <cuda_runtime.h>
#include <cstdint>

#define BATCH 2
#define SEQ   2048
#define DIM   2048
#define NH    16
#define NKV   4
#define HD    128
#define QDIM  (NH*HD)      // 2048
#define KVDIM (2*NKV*HD)   // 1024
#define ROWS  (BATCH*SEQ)  // 4096

// Scratch (allocation-free rule: __device__ globals)
__device__ float g_x32[(size_t)ROWS*DIM];     // rna(x)
__device__ float g_q  [(size_t)ROWS*QDIM];
__device__ float g_kv [(size_t)ROWS*KVDIM];
__device__ float g_vo [(size_t)ROWS*QDIM];
__device__ float g_wqt [(size_t)DIM*QDIM];    // rna(Wq^T)
__device__ float g_wkvt[(size_t)DIM*KVDIM];   // rna(Wkv^T)
__device__ float g_wot [(size_t)QDIM*DIM];    // rna(Wo^T)

__device__ __forceinline__ uint32_t tf32_rna(float x) {
    uint32_t y;
    asm("cvt.rna.tf32.f32 %0, %1;" : "=r"(y) : "f"(x));
    return y;
}
__device__ __forceinline__ float tf32f(float x) {
    return __uint_as_float(tf32_rna(x));
}
__device__ __forceinline__ float ex2f(float x) {
    float y;
    asm("ex2.approx.ftz.f32 %0, %1;" : "=f"(y) : "f"(x));
    return y;
}

#define MMA_TF32(c, a, b0, b1)                                                \
    asm volatile("mma.sync.aligned.m16n8k8.row.col.f32.tf32.tf32.f32 "        \
        "{%0,%1,%2,%3},{%4,%5,%6,%7},{%8,%9},{%0,%1,%2,%3};"                  \
        : "+f"((c)[0]), "+f"((c)[1]), "+f"((c)[2]), "+f"((c)[3])              \
        : "r"((a)[0]), "r"((a)[1]), "r"((a)[2]), "r"((a)[3]),                 \
          "r"(b0), "r"(b1))

#define CP16(d, s)   asm volatile("cp.async.cg.shared.global [%0], [%1], 16;" :: "r"(d), "l"(s))
#define CP_COMMIT()  asm volatile("cp.async.commit_group;")
#define CP_WAIT0()   asm volatile("cp.async.wait_group 0;")
#define CP_WAIT1()   asm volatile("cp.async.wait_group 1;")
#define SPTR(p)      ((uint32_t)__cvta_generic_to_shared(p))

// ---------------------------------------------------------------------------
// rna-convert x (float4 grid-stride)
// ---------------------------------------------------------------------------
__global__ void cvt_tf32_kernel(const float* __restrict__ src,
                                float* __restrict__ dst, int n4)
{
    int i = blockIdx.x * blockDim.x + threadIdx.x;
    if (i < n4) {
        float4 v = ((const float4*)src)[i];
        float4 u = { tf32f(v.x), tf32f(v.y), tf32f(v.z), tf32f(v.w) };
        ((float4*)dst)[i] = u;
    }
}

// ---------------------------------------------------------------------------
// Transpose + rna: W[K,N] -> Wt[N,K]
// ---------------------------------------------------------------------------
__global__ void transpose_kernel(const float* __restrict__ src,
                                 float* __restrict__ dst, int K, int N)
{
    __shared__ float t[32][33];
    int n0 = blockIdx.x * 32, k0 = blockIdx.y * 32;
    int x = threadIdx.x, y = threadIdx.y;     // 32 x 8
#pragma unroll
    for (int i = 0; i < 32; i += 8)
        t[y + i][x] = src[(size_t)(k0 + y + i) * N + n0 + x];
    __syncthreads();
#pragma unroll
    for (int i = 0; i < 32; i += 8)
        dst[(size_t)(n0 + y + i) * K + k0 + x] = tf32f(t[x][y + i]);
}

// ---------------------------------------------------------------------------
// TF32 mma.sync GEMM, pre-rounded inputs. 3-stage cp.async pipeline.
// CTA tile 64x128, BK=16, 256 threads = 8 warps (2m x 4n) of 32x32.
// Low register footprint -> 3 CTAs/SM.
// ---------------------------------------------------------------------------
#define SMS 20
#define A_WORDS (64*SMS)
#define B_WORDS (128*SMS)
#define STAGE_WORDS (A_WORDS + B_WORDS)
#define GEMM_SMEM (3*STAGE_WORDS*4)   // 46080 B

__global__ __launch_bounds__(256, 3) void gemm_tf32(
    const float* __restrict__ A, const float* __restrict__ Bt,
    const float* __restrict__ bias, float* __restrict__ C,
    int M, int N, int K)
{
    extern __shared__ uint32_t gsm[];

    const int tid  = threadIdx.x;
    const int lane = tid & 31, wid = tid >> 5;
    const int warp_m = (wid >> 2) << 5;   // 0 / 32
    const int warp_n = (wid & 3) << 5;    // 0 / 32 / 64 / 96
    const int g8 = lane >> 2, tg = lane & 3;
    const size_t brow0 = (size_t)blockIdx.y * 64;
    const size_t bcol0 = (size_t)blockIdx.x * 128;

    const float* Ag = A  + brow0 * K;
    const float* Bg = Bt + bcol0 * K;

    const int r0 = tid >> 2, c0 = (tid & 3) << 2;   // A: 64 rows x 4 f4; B: 2x
    const int nk = K >> 4;

    auto issue = [&](int kt, int s) {
        uint32_t* Ad = gsm + s * STAGE_WORDS;
        uint32_t* Bd = Ad + A_WORDS;
        const float* ap = Ag + (size_t)r0 * K + (kt << 4) + c0;
        const float* bp = Bg + (size_t)r0 * K + (kt << 4) + c0;
        CP16(SPTR(&Ad[r0*SMS + c0]),      ap);
        CP16(SPTR(&Bd[r0*SMS + c0]),      bp);
        CP16(SPTR(&Bd[(r0+64)*SMS + c0]), bp + (size_t)64*K);
    };

    float acc[2][4][4];
#pragma unroll
    for (int i = 0; i < 2; i++)
#pragma unroll
        for (int j = 0; j < 4; j++)
#pragma unroll
            for (int c = 0; c < 4; c++) acc[i][j][c] = 0.f;

    issue(0, 0); CP_COMMIT();
    issue(1, 1); CP_COMMIT();

    for (int kt = 0; kt < nk; kt++) {
        CP_WAIT1();
        __syncthreads();
        if (kt + 2 < nk) issue(kt + 2, (kt + 2) % 3);
        CP_COMMIT();

        const uint32_t* Ab = gsm + (kt % 3) * STAGE_WORDS;
        const uint32_t* Bb = Ab + A_WORDS;
#pragma unroll
        for (int ks = 0; ks < 2; ks++) {
            const int kb = ks << 3;
            uint32_t af[2][4], bf[4][2];
#pragma unroll
            for (int mt = 0; mt < 2; mt++) {
                const uint32_t* p = &Ab[(warp_m + mt*16 + g8)*SMS + kb + tg];
                af[mt][0] = p[0];
                af[mt][1] = p[8*SMS];
                af[mt][2] = p[4];
                af[mt][3] = p[8*SMS + 4];
            }
#pragma unroll
            for (int nt = 0; nt < 4; nt++) {
                const uint32_t* p = &Bb[(warp_n + nt*8 + g8)*SMS + kb + tg];
                bf[nt][0] = p[0];
                bf[nt][1] = p[4];
            }
#pragma unroll
            for (int mt = 0; mt < 2; mt++)
#pragma unroll
                for (int nt = 0; nt < 4; nt++)
                    MMA_TF32(acc[mt][nt], af[mt], bf[nt][0], bf[nt][1]);
        }
    }

#pragma unroll
    for (int mt = 0; mt < 2; mt++) {
#pragma unroll
        for (int nt = 0; nt < 4; nt++) {
            const size_t row = brow0 + warp_m + mt*16 + g8;
            const int    col = (int)bcol0 + warp_n + nt*8 + tg*2;
            const float b0 = bias[col], b1 = bias[col + 1];
            float2 v0 = { acc[mt][nt][0] + b0, acc[mt][nt][1] + b1 };
            float2 v1 = { acc[mt][nt][2] + b0, acc[mt][nt][3] + b1 };
            *(float2*)(C + row * N + col)       = v0;
            *(float2*)(C + (row + 8) * N + col) = v1;
        }
    }
}

// ---------------------------------------------------------------------------
// RoPE (+ softmax scale & log2e folded into q) + rna conversion of q,k,v
// ---------------------------------------------------------------------------
__global__ void rope_cvt_kernel(float* __restrict__ q, float* __restrict__ kv,
                                const float* __restrict__ cs,
                                const float* __restrict__ sn)
{
    const int row = blockIdx.x;
    const int s = row & (SEQ-1);
    const float qsc = 0.08838834764831845f * 1.4426950408889634f;
    for (int t = threadIdx.x; t < (NH+NKV)*64; t += blockDim.x) {
        int head = t >> 6, d = t & 63;
        float c  = cs[s*64 + d];
        float si = sn[s*64 + d];
        float* p1; float sc;
        if (head < NH) { p1 = q  + (size_t)row*QDIM  + head*HD + d; sc = qsc; }
        else           { p1 = kv + (size_t)row*KVDIM + (head-NH)*HD + d; sc = 1.f; }
        float* p2 = p1 + 64;
        float x1 = *p1, x2 = *p2;
        *p1 = tf32f((x1*c - x2*si) * sc);
        *p2 = tf32f((x1*si + x2*c) * sc);
    }
    // v: rna in place
    float* vb = kv + (size_t)row*KVDIM + NKV*HD;
    for (int t = threadIdx.x; t < NKV*HD; t += blockDim.x)
        vb[t] = tf32f(vb[t]);
}

// ---------------------------------------------------------------------------
// Flash attention, tf32 mma.sync.
// Single-buffered K/V (102400 B smem -> 2 CTAs/SM); cp.async fills.
// CTA = 128 q-rows x head x batch; 8 warps x 16 q-rows.
// qt REVERSED so heavy (large-nkt) tiles schedule first (causal balance).
// ---------------------------------------------------------------------------
#define FA_SMEM ((2*64*132 + 8*16*68) * 4)   // 102400 B

__global__ __launch_bounds__(256) void flash_tf32(
    const float* __restrict__ Q, const float* __restrict__ KV,
    float* __restrict__ O, const int* __restrict__ causal_p)
{
    extern __shared__ uint32_t fsm[];
    uint32_t* Ks = fsm;                  // [64*132]
    uint32_t* Vs = fsm + 64*132;         // [64*132]
    uint32_t* Ps = fsm + 2*64*132;       // [8][16*68]

    const int causal = *causal_p;
    const int qt = gridDim.x - 1 - blockIdx.x;   // heavy tiles first
    const int h = blockIdx.y, b = blockIdx.z;
    const int q0 = qt << 7;
    const int tid = threadIdx.x;
    const int lane = tid & 31, wid = tid >> 5;
    const int g8 = lane >> 2, tg = lane & 3;
    const int m0 = wid << 4;

    // ---- stage Q (pre-scaled, pre-rna) via cp.async into fsm[128][132]
    const float* Qb = Q + ((size_t)(b*SEQ + q0))*QDIM + h*HD;
    for (int i = tid; i < 128*32; i += 256) {
        int r = i >> 5, c4 = (i & 31) << 2;
        CP16(SPTR(&fsm[r*132 + c4]), Qb + (size_t)r*QDIM + c4);
    }
    CP_COMMIT(); CP_WAIT0();
    __syncthreads();

    uint32_t aq[16][4];
#pragma unroll
    for (int kb = 0; kb < 16; kb++) {
        const uint32_t* p = &fsm[(m0 + g8)*132 + kb*8 + tg];
        aq[kb][0] = p[0];
        aq[kb][1] = p[8*132];
        aq[kb][2] = p[4];
        aq[kb][3] = p[8*132 + 4];
    }

    float m_[2] = { -1e30f, -1e30f }, l_[2] = { 0.f, 0.f };
    float oacc[16][4];
#pragma unroll
    for (int nt = 0; nt < 16; nt++)
#pragma unroll
        for (int c = 0; c < 4; c++) oacc[nt][c] = 0.f;

    const int full = causal ? (q0 >> 6) : (1 << 30);
    const int nkt  = causal ? ((q0 >> 6) + 2) : (SEQ >> 6);
    const float* Kb = KV + (size_t)(b*SEQ)*KVDIM + (h >> 2)*HD;
    uint32_t* Pw = Ps + wid*16*68;

    for (int kt = 0; kt < nkt; kt++) {
        __syncthreads();                 // all warps done with prev tile & Q frag reads
        // ---- fill K,V tile (cp.async, single buffer)
        for (int i = tid; i < 64*32; i += 256) {
            int r = i >> 5, c4 = (i & 31) << 2;
            const float* kp = Kb + (size_t)((kt << 6) + r)*KVDIM + c4;
            CP16(SPTR(&Ks[r*132 + c4]), kp);
            CP16(SPTR(&Vs[r*132 + c4]), kp + NKV*HD);
        }
        CP_COMMIT(); CP_WAIT0();
        __syncthreads();

        // ---- S = Q K^T
        float sacc[8][4];
#pragma unroll
        for (int nt = 0; nt < 8; nt++)
#pragma unroll
            for (int c = 0; c < 4; c++) sacc[nt][c] = 0.f;

#pragma unroll
        for (int kb = 0; kb < 16; kb++) {
            uint32_t bf[8][2];
#pragma unroll
            for (int nt = 0; nt < 8; nt++) {
                const uint32_t* p = &Ks[(nt*8 + g8)*132 + kb*8 + tg];
                bf[nt][0] = p[0];
                bf[nt][1] = p[4];
            }
#pragma unroll
            for (int nt = 0; nt < 8; nt++)
                MMA_TF32(sacc[nt], aq[kb], bf[nt][0], bf[nt][1]);
        }

        // ---- causal mask
        if (causal && kt >= full) {
            const int row0 = q0 + m0 + g8, row1 = row0 + 8;
#pragma unroll
            for (int nt = 0; nt < 8; nt++) {
                int col = (kt << 6) + nt*8 + tg*2;
                if (col     > row0) sacc[nt][0] = -1e30f;
                if (col + 1 > row0) sacc[nt][1] = -1e30f;
                if (col     > row1) sacc[nt][2] = -1e30f;
                if (col + 1 > row1) sacc[nt][3] = -1e30f;
            }
        }

        // ---- online softmax
        float rm0 = -1e30f, rm1 = -1e30f;
#pragma unroll
        for (int nt = 0; nt < 8; nt++) {
            rm0 = fmaxf(rm0, fmaxf(sacc[nt][0], sacc[nt][1]));
            rm1 = fmaxf(rm1, fmaxf(sacc[nt][2], sacc[nt][3]));
        }
        rm0 = fmaxf(rm0, __shfl_xor_sync(0xffffffffu, rm0, 1));
        rm0 = fmaxf(rm0, __shfl_xor_sync(0xffffffffu, rm0, 2));
        rm1 = fmaxf(rm1, __shfl_xor_sync(0xffffffffu, rm1, 1));
        rm1 = fmaxf(rm1, __shfl_xor_sync(0xffffffffu, rm1, 2));

        float mn0 = fmaxf(m_[0], rm0), mn1 = fmaxf(m_[1], rm1);
        float f0 = ex2f(m_[0] - mn0), f1 = ex2f(m_[1] - mn1);
        float rs0 = 0.f, rs1 = 0.f;
#pragma unroll
        for (int nt = 0; nt < 8; nt++) {
            float p00 = ex2f(sacc[nt][0] - mn0);
            float p01 = ex2f(sacc[nt][1] - mn0);
            float p10 = ex2f(sacc[nt][2] - mn1);
            float p11 = ex2f(sacc[nt][3] - mn1);
            rs0 += p00 + p01; rs1 += p10 + p11;
            Pw[g8*68 + nt*8 + tg*2]     = tf32_rna(p00);
            Pw[g8*68 + nt*8 + tg*2 + 1] = tf32_rna(p01);
            Pw[(g8+8)*68 + nt*8 + tg*2]     = tf32_rna(p10);
            Pw[(g8+8)*68 + nt*8 + tg*2 + 1] = tf32_rna(p11);
        }
        rs0 += __shfl_xor_sync(0xffffffffu, rs0, 1);
        rs0 += __shfl_xor_sync(0xffffffffu, rs0, 2);
        rs1 += __shfl_xor_sync(0xffffffffu, rs1, 1);
        rs1 += __shfl_xor_sync(0xffffffffu, rs1, 2);
        l_[0] = l_[0]*f0 + rs0;  l_[1] = l_[1]*f1 + rs1;
        m_[0] = mn0;             m_[1] = mn1;
#pragma unroll
        for (int nt = 0; nt < 16; nt++) {
            oacc[nt][0] *= f0; oacc[nt][1] *= f0;
            oacc[nt][2] *= f1; oacc[nt][3] *= f1;
        }
        __syncwarp();

        // ---- O += P V
#pragma unroll
        for (int kb = 0; kb < 8; kb++) {
            uint32_t ap[4];
            ap[0] = Pw[g8*68 + kb*8 + tg];
            ap[1] = Pw[(g8+8)*68 + kb*8 + tg];
            ap[2] = Pw[g8*68 + kb*8 + tg + 4];
            ap[3] = Pw[(g8+8)*68 + kb*8 + tg + 4];
#pragma unroll
            for (int nt = 0; nt < 16; nt++) {
                uint32_t b0 = Vs[(kb*8 + tg)*132 + nt*8 + g8];
                uint32_t b1 = Vs[(kb*8 + tg + 4)*132 + nt*8 + g8];
                MMA_TF32(oacc[nt], ap, b0, b1);
            }
        }
        __syncwarp();
    }

    // ---- epilogue: O /= l, write rna'd (consumed by tf32 out-proj)
    const float inv0 = 1.0f / l_[0], inv1 = 1.0f / l_[1];
    float* Ob = O + ((size_t)(b*SEQ + q0 + m0))*QDIM + h*HD;
#pragma unroll
    for (int nt = 0; nt < 16; nt++) {
        float2 v0 = { tf32f(oacc[nt][0]*inv0), tf32f(oacc[nt][1]*inv0) };
        float2 v1 = { tf32f(oacc[nt][2]*inv1), tf32f(oacc[nt][3]*inv1) };
        *(float2*)(Ob + (size_t)g8*QDIM + nt*8 + tg*2)     = v0;
        *(float2*)(Ob + (size_t)(g8+8)*QDIM + nt*8 + tg*2) = v1;
    }
}

// ---------------------------------------------------------------------------
extern "C" void kernel_launch(void* const* d_in, const int* in_sizes, int n_in,
                              void* d_out, int out_size)
{
    const float* x    = (const float*)d_in[0];
    const float* cosp = (const float*)d_in[1];
    const float* sinp = (const float*)d_in[2];
    const float* Wq   = (const float*)d_in[3];
    const float* bq   = (const float*)d_in[4];
    const float* Wkv  = (const float*)d_in[5];
    const float* bkv  = (const float*)d_in[6];
    const float* Wo   = (const float*)d_in[7];
    const float* bo   = (const float*)d_in[8];
    const int*   causal = (const int*)d_in[9];
    float* out = (float*)d_out;

    float *x32, *q, *kv, *vo, *wqt, *wkvt, *wot;
    cudaGetSymbolAddress((void**)&x32,  g_x32);
    cudaGetSymbolAddress((void**)&q,    g_q);
    cudaGetSymbolAddress((void**)&kv,   g_kv);
    cudaGetSymbolAddress((void**)&vo,   g_vo);
    cudaGetSymbolAddress((void**)&wqt,  g_wqt);
    cudaGetSymbolAddress((void**)&wkvt, g_wkvt);
    cudaGetSymbolAddress((void**)&wot,  g_wot);

    cudaFuncSetAttribute(flash_tf32,
                         cudaFuncAttributeMaxDynamicSharedMemorySize, FA_SMEM);
    cudaFuncSetAttribute(gemm_tf32,
                         cudaFuncAttributeMaxDynamicSharedMemorySize, GEMM_SMEM);

    // one-time rna conversions
    cvt_tf32_kernel<<<(ROWS*DIM/4 + 255)/256, 256>>>(x, x32, ROWS*DIM/4);
    transpose_kernel<<<dim3(QDIM/32,  DIM/32),  dim3(32,8)>>>(Wq,  wqt,  DIM,  QDIM);
    transpose_kernel<<<dim3(KVDIM/32, DIM/32),  dim3(32,8)>>>(Wkv, wkvt, DIM,  KVDIM);
    transpose_kernel<<<dim3(DIM/32,   QDIM/32), dim3(32,8)>>>(Wo,  wot,  QDIM, DIM);

    gemm_tf32<<<dim3(QDIM/128,  ROWS/64), 256, GEMM_SMEM>>>(x32, wqt,  bq,  q,  ROWS, QDIM,  DIM);
    gemm_tf32<<<dim3(KVDIM/128, ROWS/64), 256, GEMM_SMEM>>>(x32, wkvt, bkv, kv, ROWS, KVDIM, DIM);

    rope_cvt_kernel<<<ROWS, 256>>>(q, kv, cosp, sinp);

    flash_tf32<<<dim3(SEQ/128, NH, BATCH), 256, FA_SMEM>>>(q, kv, vo, causal);

    gemm_tf32<<<dim3(DIM/128, ROWS/64), 256, GEMM_SMEM>>>(vo, wot, bo, out, ROWS, DIM, DIM);
}

// round 8
// speedup vs baseline: 1.1198x; 1.1198x over previous
#include <cuda_runtime.h>
#include <cstdint>

#define BATCH 2
#define SEQ   2048
#define DIM   2048
#define NH    16
#define NKV   4
#define HD    128
#define QDIM  (NH*HD)      // 2048
#define KVDIM (2*NKV*HD)   // 1024
#define ROWS  (BATCH*SEQ)  // 4096

// Scratch (allocation-free rule: __device__ globals)
__device__ float g_x32[(size_t)ROWS*DIM];     // rna(x)
__device__ float g_q  [(size_t)ROWS*QDIM];
__device__ float g_kv [(size_t)ROWS*KVDIM];
__device__ float g_vo [(size_t)ROWS*QDIM];
__device__ float g_wqt [(size_t)DIM*QDIM];    // rna(Wq^T)
__device__ float g_wkvt[(size_t)DIM*KVDIM];   // rna(Wkv^T)
__device__ float g_wot [(size_t)QDIM*DIM];    // rna(Wo^T)

__device__ __forceinline__ uint32_t tf32_rna(float x) {
    uint32_t y;
    asm("cvt.rna.tf32.f32 %0, %1;" : "=r"(y) : "f"(x));
    return y;
}
__device__ __forceinline__ float tf32f(float x) {
    return __uint_as_float(tf32_rna(x));
}
__device__ __forceinline__ float ex2f(float x) {
    float y;
    asm("ex2.approx.ftz.f32 %0, %1;" : "=f"(y) : "f"(x));
    return y;
}

#define MMA_TF32(c, a, b0, b1)                                                \
    asm volatile("mma.sync.aligned.m16n8k8.row.col.f32.tf32.tf32.f32 "        \
        "{%0,%1,%2,%3},{%4,%5,%6,%7},{%8,%9},{%0,%1,%2,%3};"                  \
        : "+f"((c)[0]), "+f"((c)[1]), "+f"((c)[2]), "+f"((c)[3])              \
        : "r"((a)[0]), "r"((a)[1]), "r"((a)[2]), "r"((a)[3]),                 \
          "r"(b0), "r"(b1))

#define CP16(d, s)   asm volatile("cp.async.cg.shared.global [%0], [%1], 16;" :: "r"(d), "l"(s))
#define CP_COMMIT()  asm volatile("cp.async.commit_group;")
#define CP_WAIT0()   asm volatile("cp.async.wait_group 0;")
#define CP_WAIT1()   asm volatile("cp.async.wait_group 1;")
#define SPTR(p)      ((uint32_t)__cvta_generic_to_shared(p))

// ---------------------------------------------------------------------------
// rna-convert x (float4 grid-stride)
// ---------------------------------------------------------------------------
__global__ void cvt_tf32_kernel(const float* __restrict__ src,
                                float* __restrict__ dst, int n4)
{
    int i = blockIdx.x * blockDim.x + threadIdx.x;
    if (i < n4) {
        float4 v = ((const float4*)src)[i];
        float4 u = { tf32f(v.x), tf32f(v.y), tf32f(v.z), tf32f(v.w) };
        ((float4*)dst)[i] = u;
    }
}

// ---------------------------------------------------------------------------
// Transpose + rna: W[K,N] -> Wt[N,K]
// ---------------------------------------------------------------------------
__global__ void transpose_kernel(const float* __restrict__ src,
                                 float* __restrict__ dst, int K, int N)
{
    __shared__ float t[32][33];
    int n0 = blockIdx.x * 32, k0 = blockIdx.y * 32;
    int x = threadIdx.x, y = threadIdx.y;     // 32 x 8
#pragma unroll
    for (int i = 0; i < 32; i += 8)
        t[y + i][x] = src[(size_t)(k0 + y + i) * N + n0 + x];
    __syncthreads();
#pragma unroll
    for (int i = 0; i < 32; i += 8)
        dst[(size_t)(n0 + y + i) * K + k0 + x] = tf32f(t[x][y + i]);
}

// ---------------------------------------------------------------------------
// TF32 mma.sync GEMM (R6 config: 128x128 tile, BK=16, 8 warps of 64x32,
// 3-stage cp.async pipeline, 2 CTAs/SM).
// ---------------------------------------------------------------------------
#define SMS 20
#define GEMM_SMEM (3*2*128*SMS*4)   // 61440 B

__global__ __launch_bounds__(256, 2) void gemm_tf32(
    const float* __restrict__ A, const float* __restrict__ Bt,
    const float* __restrict__ bias, float* __restrict__ C,
    int M, int N, int K)
{
    extern __shared__ uint32_t gsm[];
    uint32_t* As = gsm;                  // [3][128*SMS]
    uint32_t* Bs = gsm + 3*128*SMS;

    const int tid  = threadIdx.x;
    const int lane = tid & 31, wid = tid >> 5;
    const int warp_m = (wid >> 2) << 6;
    const int warp_n = (wid & 3) << 5;
    const int gr = lane >> 2, tg = lane & 3;
    const size_t brow0 = (size_t)blockIdx.y * 128;
    const size_t bcol0 = (size_t)blockIdx.x * 128;

    const float* Ag = A  + brow0 * K;
    const float* Bg = Bt + bcol0 * K;

    const int r0 = tid >> 2, c0 = (tid & 3) << 2;
    const int nk = K >> 4;

    auto issue = [&](int kt, int s) {
        uint32_t* Ad = As + s * (128*SMS);
        uint32_t* Bd = Bs + s * (128*SMS);
        const float* ap = Ag + (size_t)r0 * K + (kt << 4) + c0;
        const float* bp = Bg + (size_t)r0 * K + (kt << 4) + c0;
        CP16(SPTR(&Ad[r0*SMS + c0]),        ap);
        CP16(SPTR(&Ad[(r0+64)*SMS + c0]),   ap + (size_t)64*K);
        CP16(SPTR(&Bd[r0*SMS + c0]),        bp);
        CP16(SPTR(&Bd[(r0+64)*SMS + c0]),   bp + (size_t)64*K);
    };

    float acc[4][4][4];
#pragma unroll
    for (int i = 0; i < 4; i++)
#pragma unroll
        for (int j = 0; j < 4; j++)
#pragma unroll
            for (int c = 0; c < 4; c++) acc[i][j][c] = 0.f;

    issue(0, 0); CP_COMMIT();
    issue(1, 1); CP_COMMIT();

    for (int kt = 0; kt < nk; kt++) {
        CP_WAIT1();
        __syncthreads();
        if (kt + 2 < nk) issue(kt + 2, (kt + 2) % 3);
        CP_COMMIT();

        const uint32_t* Ab = As + (kt % 3) * (128*SMS);
        const uint32_t* Bb = Bs + (kt % 3) * (128*SMS);
#pragma unroll
        for (int ks = 0; ks < 2; ks++) {
            const int kb = ks << 3;
            uint32_t af[4][4], bf[4][2];
#pragma unroll
            for (int mt = 0; mt < 4; mt++) {
                const uint32_t* p = &Ab[(warp_m + mt*16 + gr)*SMS + kb + tg];
                af[mt][0] = p[0];
                af[mt][1] = p[8*SMS];
                af[mt][2] = p[4];
                af[mt][3] = p[8*SMS + 4];
            }
#pragma unroll
            for (int nt = 0; nt < 4; nt++) {
                const uint32_t* p = &Bb[(warp_n + nt*8 + gr)*SMS + kb + tg];
                bf[nt][0] = p[0];
                bf[nt][1] = p[4];
            }
#pragma unroll
            for (int mt = 0; mt < 4; mt++)
#pragma unroll
                for (int nt = 0; nt < 4; nt++)
                    MMA_TF32(acc[mt][nt], af[mt], bf[nt][0], bf[nt][1]);
        }
    }

#pragma unroll
    for (int mt = 0; mt < 4; mt++) {
#pragma unroll
        for (int nt = 0; nt < 4; nt++) {
            const size_t row = brow0 + warp_m + mt*16 + gr;
            const int    col = (int)bcol0 + warp_n + nt*8 + tg*2;
            const float b0 = bias[col], b1 = bias[col + 1];
            float2 v0 = { acc[mt][nt][0] + b0, acc[mt][nt][1] + b1 };
            float2 v1 = { acc[mt][nt][2] + b0, acc[mt][nt][3] + b1 };
            *(float2*)(C + row * N + col)       = v0;
            *(float2*)(C + (row + 8) * N + col) = v1;
        }
    }
}

// ---------------------------------------------------------------------------
// RoPE (+ softmax scale & log2e folded into q) + rna conversion of q,k,v
// ---------------------------------------------------------------------------
__global__ void rope_cvt_kernel(float* __restrict__ q, float* __restrict__ kv,
                                const float* __restrict__ cs,
                                const float* __restrict__ sn)
{
    const int row = blockIdx.x;
    const int s = row & (SEQ-1);
    const float qsc = 0.08838834764831845f * 1.4426950408889634f;
    for (int t = threadIdx.x; t < (NH+NKV)*64; t += blockDim.x) {
        int head = t >> 6, d = t & 63;
        float c  = cs[s*64 + d];
        float si = sn[s*64 + d];
        float* p1; float sc;
        if (head < NH) { p1 = q  + (size_t)row*QDIM  + head*HD + d; sc = qsc; }
        else           { p1 = kv + (size_t)row*KVDIM + (head-NH)*HD + d; sc = 1.f; }
        float* p2 = p1 + 64;
        float x1 = *p1, x2 = *p2;
        *p1 = tf32f((x1*c - x2*si) * sc);
        *p2 = tf32f((x1*si + x2*c) * sc);
    }
    // v: rna in place
    float* vb = kv + (size_t)row*KVDIM + NKV*HD;
    for (int t = threadIdx.x; t < NKV*HD; t += blockDim.x)
        vb[t] = tf32f(vb[t]);
}

// ---------------------------------------------------------------------------
// Flash attention, tf32 mma.sync, single-buffered K/V, cp.async fills.
// Vs stride = 136 (== 8 mod 32) -> PV B-loads conflict-free (was 2-way @132).
// Ks stride = 132 (== 4 mod 32) -> QK B-loads conflict-free (lane pattern 4*g8+tg).
// CTA = 128 q-rows x head x batch; 8 warps x 16 q-rows; qt reversed.
// ---------------------------------------------------------------------------
#define KS_W 132
#define VS_W 136
#define KS_WORDS (64*KS_W)           // 8448
#define VS_WORDS (64*VS_W)           // 8704
#define PS_OFF   (KS_WORDS + VS_WORDS)
#define FA_SMEM ((KS_WORDS + VS_WORDS + 8*16*68) * 4)   // 103424 B

__global__ __launch_bounds__(256) void flash_tf32(
    const float* __restrict__ Q, const float* __restrict__ KV,
    float* __restrict__ O, const int* __restrict__ causal_p)
{
    extern __shared__ uint32_t fsm[];
    uint32_t* Ks = fsm;                  // [64*132]
    uint32_t* Vs = fsm + KS_WORDS;       // [64*136]
    uint32_t* Ps = fsm + PS_OFF;         // [8][16*68]

    const int causal = *causal_p;
    const int qt = gridDim.x - 1 - blockIdx.x;   // heavy tiles first
    const int h = blockIdx.y, b = blockIdx.z;
    const int q0 = qt << 7;
    const int tid = threadIdx.x;
    const int lane = tid & 31, wid = tid >> 5;
    const int g8 = lane >> 2, tg = lane & 3;
    const int m0 = wid << 4;

    // ---- stage Q (pre-scaled, pre-rna) via cp.async into fsm[128][132]
    const float* Qb = Q + ((size_t)(b*SEQ + q0))*QDIM + h*HD;
    for (int i = tid; i < 128*32; i += 256) {
        int r = i >> 5, c4 = (i & 31) << 2;
        CP16(SPTR(&fsm[r*132 + c4]), Qb + (size_t)r*QDIM + c4);
    }
    CP_COMMIT(); CP_WAIT0();
    __syncthreads();

    uint32_t aq[16][4];
#pragma unroll
    for (int kb = 0; kb < 16; kb++) {
        const uint32_t* p = &fsm[(m0 + g8)*132 + kb*8 + tg];
        aq[kb][0] = p[0];
        aq[kb][1] = p[8*132];
        aq[kb][2] = p[4];
        aq[kb][3] = p[8*132 + 4];
    }

    float m_[2] = { -1e30f, -1e30f }, l_[2] = { 0.f, 0.f };
    float oacc[16][4];
#pragma unroll
    for (int nt = 0; nt < 16; nt++)
#pragma unroll
        for (int c = 0; c < 4; c++) oacc[nt][c] = 0.f;

    const int full = causal ? (q0 >> 6) : (1 << 30);
    const int nkt  = causal ? ((q0 >> 6) + 2) : (SEQ >> 6);
    const float* Kb = KV + (size_t)(b*SEQ)*KVDIM + (h >> 2)*HD;
    uint32_t* Pw = Ps + wid*16*68;

    for (int kt = 0; kt < nkt; kt++) {
        __syncthreads();                 // all warps done with prev tile & Q frag reads
        // ---- fill K,V tile (cp.async, single buffer)
        for (int i = tid; i < 64*32; i += 256) {
            int r = i >> 5, c4 = (i & 31) << 2;
            const float* kp = Kb + (size_t)((kt << 6) + r)*KVDIM + c4;
            CP16(SPTR(&Ks[r*KS_W + c4]), kp);
            CP16(SPTR(&Vs[r*VS_W + c4]), kp + NKV*HD);
        }
        CP_COMMIT(); CP_WAIT0();
        __syncthreads();

        // ---- S = Q K^T
        float sacc[8][4];
#pragma unroll
        for (int nt = 0; nt < 8; nt++)
#pragma unroll
            for (int c = 0; c < 4; c++) sacc[nt][c] = 0.f;

#pragma unroll
        for (int kb = 0; kb < 16; kb++) {
            uint32_t bf[8][2];
#pragma unroll
            for (int nt = 0; nt < 8; nt++) {
                const uint32_t* p = &Ks[(nt*8 + g8)*KS_W + kb*8 + tg];
                bf[nt][0] = p[0];
                bf[nt][1] = p[4];
            }
#pragma unroll
            for (int nt = 0; nt < 8; nt++)
                MMA_TF32(sacc[nt], aq[kb], bf[nt][0], bf[nt][1]);
        }

        // ---- causal mask
        if (causal && kt >= full) {
            const int row0 = q0 + m0 + g8, row1 = row0 + 8;
#pragma unroll
            for (int nt = 0; nt < 8; nt++) {
                int col = (kt << 6) + nt*8 + tg*2;
                if (col     > row0) sacc[nt][0] = -1e30f;
                if (col + 1 > row0) sacc[nt][1] = -1e30f;
                if (col     > row1) sacc[nt][2] = -1e30f;
                if (col + 1 > row1) sacc[nt][3] = -1e30f;
            }
        }

        // ---- online softmax
        float rm0 = -1e30f, rm1 = -1e30f;
#pragma unroll
        for (int nt = 0; nt < 8; nt++) {
            rm0 = fmaxf(rm0, fmaxf(sacc[nt][0], sacc[nt][1]));
            rm1 = fmaxf(rm1, fmaxf(sacc[nt][2], sacc[nt][3]));
        }
        rm0 = fmaxf(rm0, __shfl_xor_sync(0xffffffffu, rm0, 1));
        rm0 = fmaxf(rm0, __shfl_xor_sync(0xffffffffu, rm0, 2));
        rm1 = fmaxf(rm1, __shfl_xor_sync(0xffffffffu, rm1, 1));
        rm1 = fmaxf(rm1, __shfl_xor_sync(0xffffffffu, rm1, 2));

        float mn0 = fmaxf(m_[0], rm0), mn1 = fmaxf(m_[1], rm1);
        float f0 = ex2f(m_[0] - mn0), f1 = ex2f(m_[1] - mn1);
        float rs0 = 0.f, rs1 = 0.f;
#pragma unroll
        for (int nt = 0; nt < 8; nt++) {
            float p00 = ex2f(sacc[nt][0] - mn0);
            float p01 = ex2f(sacc[nt][1] - mn0);
            float p10 = ex2f(sacc[nt][2] - mn1);
            float p11 = ex2f(sacc[nt][3] - mn1);
            rs0 += p00 + p01; rs1 += p10 + p11;
            Pw[g8*68 + nt*8 + tg*2]     = tf32_rna(p00);
            Pw[g8*68 + nt*8 + tg*2 + 1] = tf32_rna(p01);
            Pw[(g8+8)*68 + nt*8 + tg*2]     = tf32_rna(p10);
            Pw[(g8+8)*68 + nt*8 + tg*2 + 1] = tf32_rna(p11);
        }
        rs0 += __shfl_xor_sync(0xffffffffu, rs0, 1);
        rs0 += __shfl_xor_sync(0xffffffffu, rs0, 2);
        rs1 += __shfl_xor_sync(0xffffffffu, rs1, 1);
        rs1 += __shfl_xor_sync(0xffffffffu, rs1, 2);
        l_[0] = l_[0]*f0 + rs0;  l_[1] = l_[1]*f1 + rs1;
        m_[0] = mn0;             m_[1] = mn1;
#pragma unroll
        for (int nt = 0; nt < 16; nt++) {
            oacc[nt][0] *= f0; oacc[nt][1] *= f0;
            oacc[nt][2] *= f1; oacc[nt][3] *= f1;
        }
        __syncwarp();

        // ---- O += P V (Vs stride 136: conflict-free)
#pragma unroll
        for (int kb = 0; kb < 8; kb++) {
            uint32_t ap[4];
            ap[0] = Pw[g8*68 + kb*8 + tg];
            ap[1] = Pw[(g8+8)*68 + kb*8 + tg];
            ap[2] = Pw[g8*68 + kb*8 + tg + 4];
            ap[3] = Pw[(g8+8)*68 + kb*8 + tg + 4];
#pragma unroll
            for (int nt = 0; nt < 16; nt++) {
                uint32_t b0 = Vs[(kb*8 + tg)*VS_W + nt*8 + g8];
                uint32_t b1 = Vs[(kb*8 + tg + 4)*VS_W + nt*8 + g8];
                MMA_TF32(oacc[nt], ap, b0, b1);
            }
        }
        __syncwarp();
    }

    // ---- epilogue: O /= l, write rna'd (consumed by tf32 out-proj)
    const float inv0 = 1.0f / l_[0], inv1 = 1.0f / l_[1];
    float* Ob = O + ((size_t)(b*SEQ + q0 + m0))*QDIM + h*HD;
#pragma unroll
    for (int nt = 0; nt < 16; nt++) {
        float2 v0 = { tf32f(oacc[nt][0]*inv0), tf32f(oacc[nt][1]*inv0) };
        float2 v1 = { tf32f(oacc[nt][2]*inv1), tf32f(oacc[nt][3]*inv1) };
        *(float2*)(Ob + (size_t)g8*QDIM + nt*8 + tg*2)     = v0;
        *(float2*)(Ob + (size_t)(g8+8)*QDIM + nt*8 + tg*2) = v1;
    }
}

// ---------------------------------------------------------------------------
extern "C" void kernel_launch(void* const* d_in, const int* in_sizes, int n_in,
                              void* d_out, int out_size)
{
    const float* x    = (const float*)d_in[0];
    const float* cosp = (const float*)d_in[1];
    const float* sinp = (const float*)d_in[2];
    const float* Wq   = (const float*)d_in[3];
    const float* bq   = (const float*)d_in[4];
    const float* Wkv  = (const float*)d_in[5];
    const float* bkv  = (const float*)d_in[6];
    const float* Wo   = (const float*)d_in[7];
    const float* bo   = (const float*)d_in[8];
    const int*   causal = (const int*)d_in[9];
    float* out = (float*)d_out;

    float *x32, *q, *kv, *vo, *wqt, *wkvt, *wot;
    cudaGetSymbolAddress((void**)&x32,  g_x32);
    cudaGetSymbolAddress((void**)&q,    g_q);
    cudaGetSymbolAddress((void**)&kv,   g_kv);
    cudaGetSymbolAddress((void**)&vo,   g_vo);
    cudaGetSymbolAddress((void**)&wqt,  g_wqt);
    cudaGetSymbolAddress((void**)&wkvt, g_wkvt);
    cudaGetSymbolAddress((void**)&wot,  g_wot);

    cudaFuncSetAttribute(flash_tf32,
                         cudaFuncAttributeMaxDynamicSharedMemorySize, FA_SMEM);
    cudaFuncSetAttribute(gemm_tf32,
                         cudaFuncAttributeMaxDynamicSharedMemorySize, GEMM_SMEM);

    // one-time rna conversions
    cvt_tf32_kernel<<<(ROWS*DIM/4 + 255)/256, 256>>>(x, x32, ROWS*DIM/4);
    transpose_kernel<<<dim3(QDIM/32,  DIM/32),  dim3(32,8)>>>(Wq,  wqt,  DIM,  QDIM);
    transpose_kernel<<<dim3(KVDIM/32, DIM/32),  dim3(32,8)>>>(Wkv, wkvt, DIM,  KVDIM);
    transpose_kernel<<<dim3(DIM/32,   QDIM/32), dim3(32,8)>>>(Wo,  wot,  QDIM, DIM);

    gemm_tf32<<<dim3(QDIM/128,  ROWS/128), 256, GEMM_SMEM>>>(x32, wqt,  bq,  q,  ROWS, QDIM,  DIM);
    gemm_tf32<<<dim3(KVDIM/128, ROWS/128), 256, GEMM_SMEM>>>(x32, wkvt, bkv, kv, ROWS, KVDIM, DIM);

    rope_cvt_kernel<<<ROWS, 256>>>(q, kv, cosp, sinp);

    flash_tf32<<<dim3(SEQ/128, NH, BATCH), 256, FA_SMEM>>>(q, kv, vo, causal);

    gemm_tf32<<<dim3(DIM/128, ROWS/128), 256, GEMM_SMEM>>>(vo, wot, bo, out, ROWS, DIM, DIM);
}

// round 9
// speedup vs baseline: 1.2864x; 1.1488x over previous
#include <cuda_runtime.h>
#include <cstdint>

#define BATCH 2
#define SEQ   2048
#define DIM   2048
#define NH    16
#define NKV   4
#define HD    128
#define QDIM  (NH*HD)      // 2048
#define KVDIM (2*NKV*HD)   // 1024
#define ROWS  (BATCH*SEQ)  // 4096

// Scratch (allocation-free rule: __device__ globals)
// NOTE: x32/wqt/wkvt/wot/vo are stored K-PERMUTED: within each 8-element
// k-group, order is [k0,k4,k1,k5,k2,k6,k3,k7]  (slot(j)= j<4 ? 2j : 2(j-4)+1).
// This makes tf32 mma fragment pairs (k=tg, k=tg+4) contiguous -> LDS.64.
__device__ float g_x32[(size_t)ROWS*DIM];
__device__ float g_q  [(size_t)ROWS*QDIM];     // unpermuted
__device__ float g_kv [(size_t)ROWS*KVDIM];    // unpermuted
__device__ float g_vo [(size_t)ROWS*QDIM];     // K-permuted
__device__ float g_wqt [(size_t)DIM*QDIM];
__device__ float g_wkvt[(size_t)DIM*KVDIM];
__device__ float g_wot [(size_t)QDIM*DIM];

__device__ __forceinline__ uint32_t tf32_rna(float x) {
    uint32_t y;
    asm("cvt.rna.tf32.f32 %0, %1;" : "=r"(y) : "f"(x));
    return y;
}
__device__ __forceinline__ float tf32f(float x) {
    return __uint_as_float(tf32_rna(x));
}
__device__ __forceinline__ float ex2f(float x) {
    float y;
    asm("ex2.approx.ftz.f32 %0, %1;" : "=f"(y) : "f"(x));
    return y;
}

#define MMA_TF32(c, a, b0, b1)                                                \
    asm volatile("mma.sync.aligned.m16n8k8.row.col.f32.tf32.tf32.f32 "        \
        "{%0,%1,%2,%3},{%4,%5,%6,%7},{%8,%9},{%0,%1,%2,%3};"                  \
        : "+f"((c)[0]), "+f"((c)[1]), "+f"((c)[2]), "+f"((c)[3])              \
        : "r"((a)[0]), "r"((a)[1]), "r"((a)[2]), "r"((a)[3]),                 \
          "r"(b0), "r"(b1))

#define CP16(d, s)   asm volatile("cp.async.cg.shared.global [%0], [%1], 16;" :: "r"(d), "l"(s))
#define CP_COMMIT()  asm volatile("cp.async.commit_group;")
#define CP_WAIT0()   asm volatile("cp.async.wait_group 0;")
#define CP_WAIT1()   asm volatile("cp.async.wait_group 1;")
#define SPTR(p)      ((uint32_t)__cvta_generic_to_shared(p))

// ---------------------------------------------------------------------------
// rna-convert x -> K-permuted layout
// ---------------------------------------------------------------------------
__global__ void cvt_tf32_kernel(const float* __restrict__ src,
                                float* __restrict__ dst, int n4)
{
    int i = blockIdx.x * blockDim.x + threadIdx.x;
    if (i < n4) {
        float4 v = ((const float4*)src)[i];
        // float4 i covers k-locals {0..3} (i even) or {4..7} (i odd) of group i>>1
        size_t base = ((size_t)(i >> 1) << 3) + (i & 1);
        dst[base + 0] = tf32f(v.x);
        dst[base + 2] = tf32f(v.y);
        dst[base + 4] = tf32f(v.z);
        dst[base + 6] = tf32f(v.w);
    }
}

// ---------------------------------------------------------------------------
// Transpose + rna + K-permute: W[K,N] -> Wt[N,K]
// ---------------------------------------------------------------------------
__global__ void transpose_kernel(const float* __restrict__ src,
                                 float* __restrict__ dst, int K, int N)
{
    __shared__ float t[32][33];
    int n0 = blockIdx.x * 32, k0 = blockIdx.y * 32;
    int x = threadIdx.x, y = threadIdx.y;     // 32 x 8
#pragma unroll
    for (int i = 0; i < 32; i += 8)
        t[y + i][x] = src[(size_t)(k0 + y + i) * N + n0 + x];
    __syncthreads();
    int j = x & 7;
    int px = (x & 24) + ((j < 4) ? (j << 1) : (((j - 4) << 1) | 1));
#pragma unroll
    for (int i = 0; i < 32; i += 8)
        dst[(size_t)(n0 + y + i) * K + k0 + px] = tf32f(t[x][y + i]);
}

// ---------------------------------------------------------------------------
// TF32 mma.sync GEMM on K-PERMUTED inputs.
// 128x128 tile, BK=16, 8 warps of 64x32, 3-stage cp.async pipeline.
// SMEM: unpadded 16-word rows + chunk-XOR swizzle (chunk ^ (row&3)):
//   conflict-free for 16B cp.async fill and LDS.64 fragment loads.
// ---------------------------------------------------------------------------
#define STG_WORDS 4096                   // A 128*16 + B 128*16
#define GEMM_SMEM (3*STG_WORDS*4)        // 49152 B

__global__ __launch_bounds__(256, 2) void gemm_tf32(
    const float* __restrict__ A, const float* __restrict__ Bt,
    const float* __restrict__ bias, float* __restrict__ C,
    int M, int N, int K)
{
    extern __shared__ uint32_t gsm[];

    const int tid  = threadIdx.x;
    const int lane = tid & 31, wid = tid >> 5;
    const int warp_m = (wid >> 2) << 6;
    const int warp_n = (wid & 3) << 5;
    const int g8 = lane >> 2, tg = lane & 3;
    const int sw   = g8 & 3;             // row&3 for all frag rows this thread touches
    const int coff = (tg << 1) & 3;      // word offset within chunk (0 or 2)
    const int cb0  = tg >> 1;            // chunk base (0 or 1)
    const size_t brow0 = (size_t)blockIdx.y * 128;
    const size_t bcol0 = (size_t)blockIdx.x * 128;

    const float* Ag = A  + brow0 * K;
    const float* Bg = Bt + bcol0 * K;

    const int r0 = tid >> 2, cch = tid & 3;
    const int dxor = ((cch ^ (r0 & 3)) << 2);
    const int nk = K >> 4;

    auto issue = [&](int kt, int s) {
        uint32_t* Ad = gsm + s * STG_WORDS;
        uint32_t* Bd = Ad + 2048;
        const float* ap = Ag + (size_t)r0 * K + (kt << 4) + (cch << 2);
        const float* bp = Bg + (size_t)r0 * K + (kt << 4) + (cch << 2);
        CP16(SPTR(&Ad[(r0 << 4) + dxor]),        ap);
        CP16(SPTR(&Ad[((r0 + 64) << 4) + dxor]), ap + (size_t)64 * K);
        CP16(SPTR(&Bd[(r0 << 4) + dxor]),        bp);
        CP16(SPTR(&Bd[((r0 + 64) << 4) + dxor]), bp + (size_t)64 * K);
    };

    float acc[4][4][4];
#pragma unroll
    for (int i = 0; i < 4; i++)
#pragma unroll
        for (int j = 0; j < 4; j++)
#pragma unroll
            for (int c = 0; c < 4; c++) acc[i][j][c] = 0.f;

    issue(0, 0); CP_COMMIT();
    issue(1, 1); CP_COMMIT();

    for (int kt = 0; kt < nk; kt++) {
        CP_WAIT1();
        __syncthreads();
        if (kt + 2 < nk) issue(kt + 2, (kt + 2) % 3);
        CP_COMMIT();

        const uint32_t* Ab = gsm + (kt % 3) * STG_WORDS;
        const uint32_t* Bb = Ab + 2048;
#pragma unroll
        for (int ks = 0; ks < 2; ks++) {
            const int fo = (((cb0 + (ks << 1)) ^ sw) << 2) + coff;
            uint32_t af[4][4], bf[4][2];
#pragma unroll
            for (int mt = 0; mt < 4; mt++) {
                const uint32_t* p = &Ab[((warp_m + mt*16 + g8) << 4) + fo];
                uint2 lo = *(const uint2*)p;
                uint2 hi = *(const uint2*)(p + 128);   // row +8, same xor
                af[mt][0] = lo.x; af[mt][1] = hi.x;
                af[mt][2] = lo.y; af[mt][3] = hi.y;
            }
#pragma unroll
            for (int nt = 0; nt < 4; nt++) {
                uint2 u = *(const uint2*)&Bb[((warp_n + nt*8 + g8) << 4) + fo];
                bf[nt][0] = u.x; bf[nt][1] = u.y;
            }
#pragma unroll
            for (int mt = 0; mt < 4; mt++)
#pragma unroll
                for (int nt = 0; nt < 4; nt++)
                    MMA_TF32(acc[mt][nt], af[mt], bf[nt][0], bf[nt][1]);
        }
    }

#pragma unroll
    for (int mt = 0; mt < 4; mt++) {
#pragma unroll
        for (int nt = 0; nt < 4; nt++) {
            const size_t row = brow0 + warp_m + mt*16 + g8;
            const int    col = (int)bcol0 + warp_n + nt*8 + tg*2;
            const float b0 = bias[col], b1 = bias[col + 1];
            float2 v0 = { acc[mt][nt][0] + b0, acc[mt][nt][1] + b1 };
            float2 v1 = { acc[mt][nt][2] + b0, acc[mt][nt][3] + b1 };
            *(float2*)(C + row * N + col)       = v0;
            *(float2*)(C + (row + 8) * N + col) = v1;
        }
    }
}

// ---------------------------------------------------------------------------
// RoPE (+ softmax scale & log2e folded into q) + rna conversion of q,k,v
// (unpermuted — flash consumes these directly)
// ---------------------------------------------------------------------------
__global__ void rope_cvt_kernel(float* __restrict__ q, float* __restrict__ kv,
                                const float* __restrict__ cs,
                                const float* __restrict__ sn)
{
    const int row = blockIdx.x;
    const int s = row & (SEQ-1);
    const float qsc = 0.08838834764831845f * 1.4426950408889634f;
    for (int t = threadIdx.x; t < (NH+NKV)*64; t += blockDim.x) {
        int head = t >> 6, d = t & 63;
        float c  = cs[s*64 + d];
        float si = sn[s*64 + d];
        float* p1; float sc;
        if (head < NH) { p1 = q  + (size_t)row*QDIM  + head*HD + d; sc = qsc; }
        else           { p1 = kv + (size_t)row*KVDIM + (head-NH)*HD + d; sc = 1.f; }
        float* p2 = p1 + 64;
        float x1 = *p1, x2 = *p2;
        *p1 = tf32f((x1*c - x2*si) * sc);
        *p2 = tf32f((x1*si + x2*c) * sc);
    }
    float* vb = kv + (size_t)row*KVDIM + NKV*HD;
    for (int t = threadIdx.x; t < NKV*HD; t += blockDim.x)
        vb[t] = tf32f(vb[t]);
}

// ---------------------------------------------------------------------------
// Flash attention, tf32 mma.sync, single-buffered K/V, cp.async fills.
// Identical to R8 except: vo epilogue writes K-PERMUTED slots for out-proj.
// ---------------------------------------------------------------------------
#define KS_W 132
#define VS_W 136
#define KS_WORDS (64*KS_W)
#define VS_WORDS (64*VS_W)
#define PS_OFF   (KS_WORDS + VS_WORDS)
#define FA_SMEM ((KS_WORDS + VS_WORDS + 8*16*68) * 4)   // 103424 B

__global__ __launch_bounds__(256) void flash_tf32(
    const float* __restrict__ Q, const float* __restrict__ KV,
    float* __restrict__ O, const int* __restrict__ causal_p)
{
    extern __shared__ uint32_t fsm[];
    uint32_t* Ks = fsm;                  // [64*132]
    uint32_t* Vs = fsm + KS_WORDS;       // [64*136]
    uint32_t* Ps = fsm + PS_OFF;         // [8][16*68]

    const int causal = *causal_p;
    const int qt = gridDim.x - 1 - blockIdx.x;   // heavy tiles first
    const int h = blockIdx.y, b = blockIdx.z;
    const int q0 = qt << 7;
    const int tid = threadIdx.x;
    const int lane = tid & 31, wid = tid >> 5;
    const int g8 = lane >> 2, tg = lane & 3;
    const int m0 = wid << 4;

    const float* Qb = Q + ((size_t)(b*SEQ + q0))*QDIM + h*HD;
    for (int i = tid; i < 128*32; i += 256) {
        int r = i >> 5, c4 = (i & 31) << 2;
        CP16(SPTR(&fsm[r*132 + c4]), Qb + (size_t)r*QDIM + c4);
    }
    CP_COMMIT(); CP_WAIT0();
    __syncthreads();

    uint32_t aq[16][4];
#pragma unroll
    for (int kb = 0; kb < 16; kb++) {
        const uint32_t* p = &fsm[(m0 + g8)*132 + kb*8 + tg];
        aq[kb][0] = p[0];
        aq[kb][1] = p[8*132];
        aq[kb][2] = p[4];
        aq[kb][3] = p[8*132 + 4];
    }

    float m_[2] = { -1e30f, -1e30f }, l_[2] = { 0.f, 0.f };
    float oacc[16][4];
#pragma unroll
    for (int nt = 0; nt < 16; nt++)
#pragma unroll
        for (int c = 0; c < 4; c++) oacc[nt][c] = 0.f;

    const int full = causal ? (q0 >> 6) : (1 << 30);
    const int nkt  = causal ? ((q0 >> 6) + 2) : (SEQ >> 6);
    const float* Kb = KV + (size_t)(b*SEQ)*KVDIM + (h >> 2)*HD;
    uint32_t* Pw = Ps + wid*16*68;

    for (int kt = 0; kt < nkt; kt++) {
        __syncthreads();
        for (int i = tid; i < 64*32; i += 256) {
            int r = i >> 5, c4 = (i & 31) << 2;
            const float* kp = Kb + (size_t)((kt << 6) + r)*KVDIM + c4;
            CP16(SPTR(&Ks[r*KS_W + c4]), kp);
            CP16(SPTR(&Vs[r*VS_W + c4]), kp + NKV*HD);
        }
        CP_COMMIT(); CP_WAIT0();
        __syncthreads();

        float sacc[8][4];
#pragma unroll
        for (int nt = 0; nt < 8; nt++)
#pragma unroll
            for (int c = 0; c < 4; c++) sacc[nt][c] = 0.f;

#pragma unroll
        for (int kb = 0; kb < 16; kb++) {
            uint32_t bf[8][2];
#pragma unroll
            for (int nt = 0; nt < 8; nt++) {
                const uint32_t* p = &Ks[(nt*8 + g8)*KS_W + kb*8 + tg];
                bf[nt][0] = p[0];
                bf[nt][1] = p[4];
            }
#pragma unroll
            for (int nt = 0; nt < 8; nt++)
                MMA_TF32(sacc[nt], aq[kb], bf[nt][0], bf[nt][1]);
        }

        if (causal && kt >= full) {
            const int row0 = q0 + m0 + g8, row1 = row0 + 8;
#pragma unroll
            for (int nt = 0; nt < 8; nt++) {
                int col = (kt << 6) + nt*8 + tg*2;
                if (col     > row0) sacc[nt][0] = -1e30f;
                if (col + 1 > row0) sacc[nt][1] = -1e30f;
                if (col     > row1) sacc[nt][2] = -1e30f;
                if (col + 1 > row1) sacc[nt][3] = -1e30f;
            }
        }

        float rm0 = -1e30f, rm1 = -1e30f;
#pragma unroll
        for (int nt = 0; nt < 8; nt++) {
            rm0 = fmaxf(rm0, fmaxf(sacc[nt][0], sacc[nt][1]));
            rm1 = fmaxf(rm1, fmaxf(sacc[nt][2], sacc[nt][3]));
        }
        rm0 = fmaxf(rm0, __shfl_xor_sync(0xffffffffu, rm0, 1));
        rm0 = fmaxf(rm0, __shfl_xor_sync(0xffffffffu, rm0, 2));
        rm1 = fmaxf(rm1, __shfl_xor_sync(0xffffffffu, rm1, 1));
        rm1 = fmaxf(rm1, __shfl_xor_sync(0xffffffffu, rm1, 2));

        float mn0 = fmaxf(m_[0], rm0), mn1 = fmaxf(m_[1], rm1);
        float f0 = ex2f(m_[0] - mn0), f1 = ex2f(m_[1] - mn1);
        float rs0 = 0.f, rs1 = 0.f;
#pragma unroll
        for (int nt = 0; nt < 8; nt++) {
            float p00 = ex2f(sacc[nt][0] - mn0);
            float p01 = ex2f(sacc[nt][1] - mn0);
            float p10 = ex2f(sacc[nt][2] - mn1);
            float p11 = ex2f(sacc[nt][3] - mn1);
            rs0 += p00 + p01; rs1 += p10 + p11;
            Pw[g8*68 + nt*8 + tg*2]     = tf32_rna(p00);
            Pw[g8*68 + nt*8 + tg*2 + 1] = tf32_rna(p01);
            Pw[(g8+8)*68 + nt*8 + tg*2]     = tf32_rna(p10);
            Pw[(g8+8)*68 + nt*8 + tg*2 + 1] = tf32_rna(p11);
        }
        rs0 += __shfl_xor_sync(0xffffffffu, rs0, 1);
        rs0 += __shfl_xor_sync(0xffffffffu, rs0, 2);
        rs1 += __shfl_xor_sync(0xffffffffu, rs1, 1);
        rs1 += __shfl_xor_sync(0xffffffffu, rs1, 2);
        l_[0] = l_[0]*f0 + rs0;  l_[1] = l_[1]*f1 + rs1;
        m_[0] = mn0;             m_[1] = mn1;
#pragma unroll
        for (int nt = 0; nt < 16; nt++) {
            oacc[nt][0] *= f0; oacc[nt][1] *= f0;
            oacc[nt][2] *= f1; oacc[nt][3] *= f1;
        }
        __syncwarp();

#pragma unroll
        for (int kb = 0; kb < 8; kb++) {
            uint32_t ap[4];
            ap[0] = Pw[g8*68 + kb*8 + tg];
            ap[1] = Pw[(g8+8)*68 + kb*8 + tg];
            ap[2] = Pw[g8*68 + kb*8 + tg + 4];
            ap[3] = Pw[(g8+8)*68 + kb*8 + tg + 4];
#pragma unroll
            for (int nt = 0; nt < 16; nt++) {
                uint32_t b0 = Vs[(kb*8 + tg)*VS_W + nt*8 + g8];
                uint32_t b1 = Vs[(kb*8 + tg + 4)*VS_W + nt*8 + g8];
                MMA_TF32(oacc[nt], ap, b0, b1);
            }
        }
        __syncwarp();
    }

    // ---- epilogue: O /= l, write rna'd into K-PERMUTED slots for out-proj.
    // col 2tg   -> slot {0,4,1,5}[tg];  col 2tg+1 -> slot+2
    const float inv0 = 1.0f / l_[0], inv1 = 1.0f / l_[1];
    const int s0 = (tg < 2) ? (tg << 2) : (((tg - 2) << 2) | 1);
    float* Ob = O + ((size_t)(b*SEQ + q0 + m0))*QDIM + h*HD;
#pragma unroll
    for (int nt = 0; nt < 16; nt++) {
        const int base = nt*8;
        Ob[(size_t)g8*QDIM + base + s0]         = tf32f(oacc[nt][0]*inv0);
        Ob[(size_t)g8*QDIM + base + s0 + 2]     = tf32f(oacc[nt][1]*inv0);
        Ob[(size_t)(g8+8)*QDIM + base + s0]     = tf32f(oacc[nt][2]*inv1);
        Ob[(size_t)(g8+8)*QDIM + base + s0 + 2] = tf32f(oacc[nt][3]*inv1);
    }
}

// ---------------------------------------------------------------------------
extern "C" void kernel_launch(void* const* d_in, const int* in_sizes, int n_in,
                              void* d_out, int out_size)
{
    const float* x    = (const float*)d_in[0];
    const float* cosp = (const float*)d_in[1];
    const float* sinp = (const float*)d_in[2];
    const float* Wq   = (const float*)d_in[3];
    const float* bq   = (const float*)d_in[4];
    const float* Wkv  = (const float*)d_in[5];
    const float* bkv  = (const float*)d_in[6];
    const float* Wo   = (const float*)d_in[7];
    const float* bo   = (const float*)d_in[8];
    const int*   causal = (const int*)d_in[9];
    float* out = (float*)d_out;

    float *x32, *q, *kv, *vo, *wqt, *wkvt, *wot;
    cudaGetSymbolAddress((void**)&x32,  g_x32);
    cudaGetSymbolAddress((void**)&q,    g_q);
    cudaGetSymbolAddress((void**)&kv,   g_kv);
    cudaGetSymbolAddress((void**)&vo,   g_vo);
    cudaGetSymbolAddress((void**)&wqt,  g_wqt);
    cudaGetSymbolAddress((void**)&wkvt, g_wkvt);
    cudaGetSymbolAddress((void**)&wot,  g_wot);

    cudaFuncSetAttribute(flash_tf32,
                         cudaFuncAttributeMaxDynamicSharedMemorySize, FA_SMEM);
    cudaFuncSetAttribute(gemm_tf32,
                         cudaFuncAttributeMaxDynamicSharedMemorySize, GEMM_SMEM);

    // one-time rna conversions (K-permuted layouts)
    cvt_tf32_kernel<<<(ROWS*DIM/4 + 255)/256, 256>>>(x, x32, ROWS*DIM/4);
    transpose_kernel<<<dim3(QDIM/32,  DIM/32),  dim3(32,8)>>>(Wq,  wqt,  DIM,  QDIM);
    transpose_kernel<<<dim3(KVDIM/32, DIM/32),  dim3(32,8)>>>(Wkv, wkvt, DIM,  KVDIM);
    transpose_kernel<<<dim3(DIM/32,   QDIM/32), dim3(32,8)>>>(Wo,  wot,  QDIM, DIM);

    gemm_tf32<<<dim3(QDIM/128,  ROWS/128), 256, GEMM_SMEM>>>(x32, wqt,  bq,  q,  ROWS, QDIM,  DIM);
    gemm_tf32<<<dim3(KVDIM/128, ROWS/128), 256, GEMM_SMEM>>>(x32, wkvt, bkv, kv, ROWS, KVDIM, DIM);

    rope_cvt_kernel<<<ROWS, 256>>>(q, kv, cosp, sinp);

    flash_tf32<<<dim3(SEQ/128, NH, BATCH), 256, FA_SMEM>>>(q, kv, vo, causal);

    gemm_tf32<<<dim3(DIM/128, ROWS/128), 256, GEMM_SMEM>>>(vo, wot, bo, out, ROWS, DIM, DIM);
}

// round 10
// speedup vs baseline: 1.3275x; 1.0319x over previous
#include <cuda_runtime.h>
#include <cstdint>

#define BATCH 2
#define SEQ   2048
#define DIM   2048
#define NH    16
#define NKV   4
#define HD    128
#define QDIM  (NH*HD)      // 2048
#define KVDIM (2*NKV*HD)   // 1024
#define ROWS  (BATCH*SEQ)  // 4096

// Scratch (allocation-free rule: __device__ globals)
// K-PERMUTED layouts (per 8-elem k-group: [k0,k4,k1,k5,k2,k6,k3,k7]):
//   x32, wqt, wkvt, wot, vo            (gemm K dim)
//   g_q and K-half of g_kv (head dim)  (flash QK k dim)
__device__ float g_x32[(size_t)ROWS*DIM];
__device__ float g_q  [(size_t)ROWS*QDIM];
__device__ float g_kv [(size_t)ROWS*KVDIM];
__device__ float g_vo [(size_t)ROWS*QDIM];
__device__ float g_wqt [(size_t)DIM*QDIM];
__device__ float g_wkvt[(size_t)DIM*KVDIM];
__device__ float g_wot [(size_t)QDIM*DIM];

__device__ __forceinline__ uint32_t tf32_rna(float x) {
    uint32_t y;
    asm("cvt.rna.tf32.f32 %0, %1;" : "=r"(y) : "f"(x));
    return y;
}
__device__ __forceinline__ float tf32f(float x) {
    return __uint_as_float(tf32_rna(x));
}
__device__ __forceinline__ float ex2f(float x) {
    float y;
    asm("ex2.approx.ftz.f32 %0, %1;" : "=f"(y) : "f"(x));
    return y;
}
// slot(j) = ((j&3)<<1) | (j>>2)  for j in 0..7  -> [0,2,4,6,1,3,5,7]
__device__ __forceinline__ int kslot(int j) { return ((j & 3) << 1) | (j >> 2); }

#define MMA_TF32(c, a, b0, b1)                                                \
    asm volatile("mma.sync.aligned.m16n8k8.row.col.f32.tf32.tf32.f32 "        \
        "{%0,%1,%2,%3},{%4,%5,%6,%7},{%8,%9},{%0,%1,%2,%3};"                  \
        : "+f"((c)[0]), "+f"((c)[1]), "+f"((c)[2]), "+f"((c)[3])              \
        : "r"((a)[0]), "r"((a)[1]), "r"((a)[2]), "r"((a)[3]),                 \
          "r"(b0), "r"(b1))

#define CP16(d, s)   asm volatile("cp.async.cg.shared.global [%0], [%1], 16;" :: "r"(d), "l"(s))
#define CP_COMMIT()  asm volatile("cp.async.commit_group;")
#define CP_WAIT0()   asm volatile("cp.async.wait_group 0;")
#define CP_WAIT1()   asm volatile("cp.async.wait_group 1;")
#define SPTR(p)      ((uint32_t)__cvta_generic_to_shared(p))

// ---------------------------------------------------------------------------
// rna-convert x -> K-permuted layout
// ---------------------------------------------------------------------------
__global__ void cvt_tf32_kernel(const float* __restrict__ src,
                                float* __restrict__ dst, int n4)
{
    int i = blockIdx.x * blockDim.x + threadIdx.x;
    if (i < n4) {
        float4 v = ((const float4*)src)[i];
        size_t base = ((size_t)(i >> 1) << 3) + (i & 1);
        dst[base + 0] = tf32f(v.x);
        dst[base + 2] = tf32f(v.y);
        dst[base + 4] = tf32f(v.z);
        dst[base + 6] = tf32f(v.w);
    }
}

// ---------------------------------------------------------------------------
// Transpose + rna + K-permute: W[K,N] -> Wt[N,K]
// ---------------------------------------------------------------------------
__global__ void transpose_kernel(const float* __restrict__ src,
                                 float* __restrict__ dst, int K, int N)
{
    __shared__ float t[32][33];
    int n0 = blockIdx.x * 32, k0 = blockIdx.y * 32;
    int x = threadIdx.x, y = threadIdx.y;     // 32 x 8
#pragma unroll
    for (int i = 0; i < 32; i += 8)
        t[y + i][x] = src[(size_t)(k0 + y + i) * N + n0 + x];
    __syncthreads();
    int px = (x & 24) + kslot(x & 7);
#pragma unroll
    for (int i = 0; i < 32; i += 8)
        dst[(size_t)(n0 + y + i) * K + k0 + px] = tf32f(t[x][y + i]);
}

// ---------------------------------------------------------------------------
// TF32 mma.sync GEMM on K-PERMUTED inputs (unchanged from R9).
// ---------------------------------------------------------------------------
#define STG_WORDS 4096
#define GEMM_SMEM (3*STG_WORDS*4)        // 49152 B

__global__ __launch_bounds__(256, 2) void gemm_tf32(
    const float* __restrict__ A, const float* __restrict__ Bt,
    const float* __restrict__ bias, float* __restrict__ C,
    int M, int N, int K)
{
    extern __shared__ uint32_t gsm[];

    const int tid  = threadIdx.x;
    const int lane = tid & 31, wid = tid >> 5;
    const int warp_m = (wid >> 2) << 6;
    const int warp_n = (wid & 3) << 5;
    const int g8 = lane >> 2, tg = lane & 3;
    const int sw   = g8 & 3;
    const int coff = (tg << 1) & 3;
    const int cb0  = tg >> 1;
    const size_t brow0 = (size_t)blockIdx.y * 128;
    const size_t bcol0 = (size_t)blockIdx.x * 128;

    const float* Ag = A  + brow0 * K;
    const float* Bg = Bt + bcol0 * K;

    const int r0 = tid >> 2, cch = tid & 3;
    const int dxor = ((cch ^ (r0 & 3)) << 2);
    const int nk = K >> 4;

    auto issue = [&](int kt, int s) {
        uint32_t* Ad = gsm + s * STG_WORDS;
        uint32_t* Bd = Ad + 2048;
        const float* ap = Ag + (size_t)r0 * K + (kt << 4) + (cch << 2);
        const float* bp = Bg + (size_t)r0 * K + (kt << 4) + (cch << 2);
        CP16(SPTR(&Ad[(r0 << 4) + dxor]),        ap);
        CP16(SPTR(&Ad[((r0 + 64) << 4) + dxor]), ap + (size_t)64 * K);
        CP16(SPTR(&Bd[(r0 << 4) + dxor]),        bp);
        CP16(SPTR(&Bd[((r0 + 64) << 4) + dxor]), bp + (size_t)64 * K);
    };

    float acc[4][4][4];
#pragma unroll
    for (int i = 0; i < 4; i++)
#pragma unroll
        for (int j = 0; j < 4; j++)
#pragma unroll
            for (int c = 0; c < 4; c++) acc[i][j][c] = 0.f;

    issue(0, 0); CP_COMMIT();
    issue(1, 1); CP_COMMIT();

    for (int kt = 0; kt < nk; kt++) {
        CP_WAIT1();
        __syncthreads();
        if (kt + 2 < nk) issue(kt + 2, (kt + 2) % 3);
        CP_COMMIT();

        const uint32_t* Ab = gsm + (kt % 3) * STG_WORDS;
        const uint32_t* Bb = Ab + 2048;
#pragma unroll
        for (int ks = 0; ks < 2; ks++) {
            const int fo = (((cb0 + (ks << 1)) ^ sw) << 2) + coff;
            uint32_t af[4][4], bf[4][2];
#pragma unroll
            for (int mt = 0; mt < 4; mt++) {
                const uint32_t* p = &Ab[((warp_m + mt*16 + g8) << 4) + fo];
                uint2 lo = *(const uint2*)p;
                uint2 hi = *(const uint2*)(p + 128);
                af[mt][0] = lo.x; af[mt][1] = hi.x;
                af[mt][2] = lo.y; af[mt][3] = hi.y;
            }
#pragma unroll
            for (int nt = 0; nt < 4; nt++) {
                uint2 u = *(const uint2*)&Bb[((warp_n + nt*8 + g8) << 4) + fo];
                bf[nt][0] = u.x; bf[nt][1] = u.y;
            }
#pragma unroll
            for (int mt = 0; mt < 4; mt++)
#pragma unroll
                for (int nt = 0; nt < 4; nt++)
                    MMA_TF32(acc[mt][nt], af[mt], bf[nt][0], bf[nt][1]);
        }
    }

#pragma unroll
    for (int mt = 0; mt < 4; mt++) {
#pragma unroll
        for (int nt = 0; nt < 4; nt++) {
            const size_t row = brow0 + warp_m + mt*16 + g8;
            const int    col = (int)bcol0 + warp_n + nt*8 + tg*2;
            const float b0 = bias[col], b1 = bias[col + 1];
            float2 v0 = { acc[mt][nt][0] + b0, acc[mt][nt][1] + b1 };
            float2 v1 = { acc[mt][nt][2] + b0, acc[mt][nt][3] + b1 };
            *(float2*)(C + row * N + col)       = v0;
            *(float2*)(C + (row + 8) * N + col) = v1;
        }
    }
}

// ---------------------------------------------------------------------------
// RoPE + rna; Q and K written HEAD-DIM PERMUTED (flash QK fragment layout).
// V unpermuted.
// ---------------------------------------------------------------------------
__global__ void rope_cvt_kernel(float* __restrict__ q, float* __restrict__ kv,
                                const float* __restrict__ cs,
                                const float* __restrict__ sn)
{
    const int row = blockIdx.x;
    const int s = row & (SEQ-1);
    const float qsc = 0.08838834764831845f * 1.4426950408889634f;
    for (int t = threadIdx.x; t < (NH+NKV)*64; t += blockDim.x) {
        int head = t >> 6, d = t & 63;
        float c  = cs[s*64 + d];
        float si = sn[s*64 + d];
        float* base; float sc;
        if (head < NH) { base = q  + (size_t)row*QDIM  + head*HD; sc = qsc; }
        else           { base = kv + (size_t)row*KVDIM + (head-NH)*HD; sc = 1.f; }
        float x1 = base[d], x2 = base[d + 64];
        int p1 = (d & 56)        + kslot(d & 7);
        int p2 = ((d + 64) & ~7) + kslot(d & 7);
        base[p1] = tf32f((x1*c - x2*si) * sc);
        base[p2] = tf32f((x1*si + x2*c) * sc);
    }
    float* vb = kv + (size_t)row*KVDIM + NKV*HD;
    for (int t = threadIdx.x; t < NKV*HD; t += blockDim.x)
        vb[t] = tf32f(vb[t]);
}

// ---------------------------------------------------------------------------
// Flash attention, tf32 mma.sync, single-buffered K/V.
//  - Q/K head-dim permuted -> QK frag loads are LDS.64 (stride 136, CF)
//  - P buffer permuted     -> PV A-frag loads are LDS.64 (stride 72, CF)
//  - K and V committed as separate cp.async groups: V load overlaps S+softmax
// ---------------------------------------------------------------------------
#define KV_W 136
#define KV_WORDS (64*KV_W)               // 8704
#define PW_W 72
#define PS_OFF   (2*KV_WORDS)
#define FA_SMEM ((2*KV_WORDS + 8*16*PW_W) * 4)   // 106496 B

__global__ __launch_bounds__(256) void flash_tf32(
    const float* __restrict__ Q, const float* __restrict__ KV,
    float* __restrict__ O, const int* __restrict__ causal_p)
{
    extern __shared__ uint32_t fsm[];
    uint32_t* Ks = fsm;                  // [64*136]
    uint32_t* Vs = fsm + KV_WORDS;       // [64*136]
    uint32_t* Ps = fsm + PS_OFF;         // [8][16*72]

    const int causal = *causal_p;
    const int qt = gridDim.x - 1 - blockIdx.x;   // heavy tiles first
    const int h = blockIdx.y, b = blockIdx.z;
    const int q0 = qt << 7;
    const int tid = threadIdx.x;
    const int lane = tid & 31, wid = tid >> 5;
    const int g8 = lane >> 2, tg = lane & 3;
    const int m0 = wid << 4;
    const int sl0 = kslot(2*tg), sl1 = kslot(2*tg + 1);

    // ---- stage Q (permuted) via cp.async into fsm[128][136]
    const float* Qb = Q + ((size_t)(b*SEQ + q0))*QDIM + h*HD;
    for (int i = tid; i < 128*32; i += 256) {
        int r = i >> 5, c4 = (i & 31) << 2;
        CP16(SPTR(&fsm[r*KV_W + c4]), Qb + (size_t)r*QDIM + c4);
    }
    CP_COMMIT(); CP_WAIT0();
    __syncthreads();

    uint32_t aq[16][4];
#pragma unroll
    for (int kb = 0; kb < 16; kb++) {
        const uint32_t* p = &fsm[(m0 + g8)*KV_W + kb*8 + 2*tg];
        uint2 lo = *(const uint2*)p;
        uint2 hi = *(const uint2*)(p + 8*KV_W);
        aq[kb][0] = lo.x; aq[kb][2] = lo.y;
        aq[kb][1] = hi.x; aq[kb][3] = hi.y;
    }

    float m_[2] = { -1e30f, -1e30f }, l_[2] = { 0.f, 0.f };
    float oacc[16][4];
#pragma unroll
    for (int nt = 0; nt < 16; nt++)
#pragma unroll
        for (int c = 0; c < 4; c++) oacc[nt][c] = 0.f;

    const int full = causal ? (q0 >> 6) : (1 << 30);
    const int nkt  = causal ? ((q0 >> 6) + 2) : (SEQ >> 6);
    const float* Kb = KV + (size_t)(b*SEQ)*KVDIM + (h >> 2)*HD;
    uint32_t* Pw = Ps + wid*16*PW_W;

    for (int kt = 0; kt < nkt; kt++) {
        __syncthreads();                 // prev tile fully consumed
        // ---- K group
        for (int i = tid; i < 64*32; i += 256) {
            int r = i >> 5, c4 = (i & 31) << 2;
            CP16(SPTR(&Ks[r*KV_W + c4]),
                 Kb + (size_t)((kt << 6) + r)*KVDIM + c4);
        }
        CP_COMMIT();
        // ---- V group (overlaps with S + softmax below)
        for (int i = tid; i < 64*32; i += 256) {
            int r = i >> 5, c4 = (i & 31) << 2;
            CP16(SPTR(&Vs[r*KV_W + c4]),
                 Kb + (size_t)((kt << 6) + r)*KVDIM + NKV*HD + c4);
        }
        CP_COMMIT();
        CP_WAIT1();                      // K arrived (V may still be in flight)
        __syncthreads();

        // ---- S = Q K^T (permuted frags, LDS.64)
        float sacc[8][4];
#pragma unroll
        for (int nt = 0; nt < 8; nt++)
#pragma unroll
            for (int c = 0; c < 4; c++) sacc[nt][c] = 0.f;

#pragma unroll
        for (int kb = 0; kb < 16; kb++) {
            uint32_t bf[8][2];
#pragma unroll
            for (int nt = 0; nt < 8; nt++) {
                uint2 u = *(const uint2*)&Ks[(nt*8 + g8)*KV_W + kb*8 + 2*tg];
                bf[nt][0] = u.x;
                bf[nt][1] = u.y;
            }
#pragma unroll
            for (int nt = 0; nt < 8; nt++)
                MMA_TF32(sacc[nt], aq[kb], bf[nt][0], bf[nt][1]);
        }

        // ---- causal mask
        if (causal && kt >= full) {
            const int row0 = q0 + m0 + g8, row1 = row0 + 8;
#pragma unroll
            for (int nt = 0; nt < 8; nt++) {
                int col = (kt << 6) + nt*8 + tg*2;
                if (col     > row0) sacc[nt][0] = -1e30f;
                if (col + 1 > row0) sacc[nt][1] = -1e30f;
                if (col     > row1) sacc[nt][2] = -1e30f;
                if (col + 1 > row1) sacc[nt][3] = -1e30f;
            }
        }

        // ---- online softmax; P written into PERMUTED slots
        float rm0 = -1e30f, rm1 = -1e30f;
#pragma unroll
        for (int nt = 0; nt < 8; nt++) {
            rm0 = fmaxf(rm0, fmaxf(sacc[nt][0], sacc[nt][1]));
            rm1 = fmaxf(rm1, fmaxf(sacc[nt][2], sacc[nt][3]));
        }
        rm0 = fmaxf(rm0, __shfl_xor_sync(0xffffffffu, rm0, 1));
        rm0 = fmaxf(rm0, __shfl_xor_sync(0xffffffffu, rm0, 2));
        rm1 = fmaxf(rm1, __shfl_xor_sync(0xffffffffu, rm1, 1));
        rm1 = fmaxf(rm1, __shfl_xor_sync(0xffffffffu, rm1, 2));

        float mn0 = fmaxf(m_[0], rm0), mn1 = fmaxf(m_[1], rm1);
        float f0 = ex2f(m_[0] - mn0), f1 = ex2f(m_[1] - mn1);
        float rs0 = 0.f, rs1 = 0.f;
#pragma unroll
        for (int nt = 0; nt < 8; nt++) {
            float p00 = ex2f(sacc[nt][0] - mn0);
            float p01 = ex2f(sacc[nt][1] - mn0);
            float p10 = ex2f(sacc[nt][2] - mn1);
            float p11 = ex2f(sacc[nt][3] - mn1);
            rs0 += p00 + p01; rs1 += p10 + p11;
            Pw[g8*PW_W + nt*8 + sl0]     = tf32_rna(p00);
            Pw[g8*PW_W + nt*8 + sl1]     = tf32_rna(p01);
            Pw[(g8+8)*PW_W + nt*8 + sl0] = tf32_rna(p10);
            Pw[(g8+8)*PW_W + nt*8 + sl1] = tf32_rna(p11);
        }
        rs0 += __shfl_xor_sync(0xffffffffu, rs0, 1);
        rs0 += __shfl_xor_sync(0xffffffffu, rs0, 2);
        rs1 += __shfl_xor_sync(0xffffffffu, rs1, 1);
        rs1 += __shfl_xor_sync(0xffffffffu, rs1, 2);
        l_[0] = l_[0]*f0 + rs0;  l_[1] = l_[1]*f1 + rs1;
        m_[0] = mn0;             m_[1] = mn1;
#pragma unroll
        for (int nt = 0; nt < 16; nt++) {
            oacc[nt][0] *= f0; oacc[nt][1] *= f0;
            oacc[nt][2] *= f1; oacc[nt][3] *= f1;
        }

        CP_WAIT0();                      // V arrived
        __syncthreads();                 // all threads' V copies visible

        // ---- O += P V  (P frag via LDS.64)
#pragma unroll
        for (int kb = 0; kb < 8; kb++) {
            uint32_t ap[4];
            uint2 plo = *(const uint2*)&Pw[g8*PW_W + kb*8 + 2*tg];
            uint2 phi = *(const uint2*)&Pw[(g8+8)*PW_W + kb*8 + 2*tg];
            ap[0] = plo.x; ap[2] = plo.y;
            ap[1] = phi.x; ap[3] = phi.y;
#pragma unroll
            for (int nt = 0; nt < 16; nt++) {
                uint32_t b0 = Vs[(kb*8 + tg)*KV_W + nt*8 + g8];
                uint32_t b1 = Vs[(kb*8 + tg + 4)*KV_W + nt*8 + g8];
                MMA_TF32(oacc[nt], ap, b0, b1);
            }
        }
    }

    // ---- epilogue: O /= l, write rna'd into K-PERMUTED slots for out-proj
    const float inv0 = 1.0f / l_[0], inv1 = 1.0f / l_[1];
    const int s0 = (tg < 2) ? (tg << 2) : (((tg - 2) << 2) | 1);
    float* Ob = O + ((size_t)(b*SEQ + q0 + m0))*QDIM + h*HD;
#pragma unroll
    for (int nt = 0; nt < 16; nt++) {
        const int base = nt*8;
        Ob[(size_t)g8*QDIM + base + s0]         = tf32f(oacc[nt][0]*inv0);
        Ob[(size_t)g8*QDIM + base + s0 + 2]     = tf32f(oacc[nt][1]*inv0);
        Ob[(size_t)(g8+8)*QDIM + base + s0]     = tf32f(oacc[nt][2]*inv1);
        Ob[(size_t)(g8+8)*QDIM + base + s0 + 2] = tf32f(oacc[nt][3]*inv1);
    }
}

// ---------------------------------------------------------------------------
extern "C" void kernel_launch(void* const* d_in, const int* in_sizes, int n_in,
                              void* d_out, int out_size)
{
    const float* x    = (const float*)d_in[0];
    const float* cosp = (const float*)d_in[1];
    const float* sinp = (const float*)d_in[2];
    const float* Wq   = (const float*)d_in[3];
    const float* bq   = (const float*)d_in[4];
    const float* Wkv  = (const float*)d_in[5];
    const float* bkv  = (const float*)d_in[6];
    const float* Wo   = (const float*)d_in[7];
    const float* bo   = (const float*)d_in[8];
    const int*   causal = (const int*)d_in[9];
    float* out = (float*)d_out;

    float *x32, *q, *kv, *vo, *wqt, *wkvt, *wot;
    cudaGetSymbolAddress((void**)&x32,  g_x32);
    cudaGetSymbolAddress((void**)&q,    g_q);
    cudaGetSymbolAddress((void**)&kv,   g_kv);
    cudaGetSymbolAddress((void**)&vo,   g_vo);
    cudaGetSymbolAddress((void**)&wqt,  g_wqt);
    cudaGetSymbolAddress((void**)&wkvt, g_wkvt);
    cudaGetSymbolAddress((void**)&wot,  g_wot);

    cudaFuncSetAttribute(flash_tf32,
                         cudaFuncAttributeMaxDynamicSharedMemorySize, FA_SMEM);
    cudaFuncSetAttribute(gemm_tf32,
                         cudaFuncAttributeMaxDynamicSharedMemorySize, GEMM_SMEM);

    cvt_tf32_kernel<<<(ROWS*DIM/4 + 255)/256, 256>>>(x, x32, ROWS*DIM/4);
    transpose_kernel<<<dim3(QDIM/32,  DIM/32),  dim3(32,8)>>>(Wq,  wqt,  DIM,  QDIM);
    transpose_kernel<<<dim3(KVDIM/32, DIM/32),  dim3(32,8)>>>(Wkv, wkvt, DIM,  KVDIM);
    transpose_kernel<<<dim3(DIM/32,   QDIM/32), dim3(32,8)>>>(Wo,  wot,  QDIM, DIM);

    gemm_tf32<<<dim3(QDIM/128,  ROWS/128), 256, GEMM_SMEM>>>(x32, wqt,  bq,  q,  ROWS, QDIM,  DIM);
    gemm_tf32<<<dim3(KVDIM/128, ROWS/128), 256, GEMM_SMEM>>>(x32, wkvt, bkv, kv, ROWS, KVDIM, DIM);

    rope_cvt_kernel<<<ROWS, 256>>>(q, kv, cosp, sinp);

    flash_tf32<<<dim3(SEQ/128, NH, BATCH), 256, FA_SMEM>>>(q, kv, vo, causal);

    gemm_tf32<<<dim3(DIM/128, ROWS/128), 256, GEMM_SMEM>>>(vo, wot, bo, out, ROWS, DIM, DIM);
}